// round 17
// baseline (speedup 1.0000x reference)
#include <cuda_runtime.h>
#include <cstdint>

// RGBuvHistBlock: x [8,3,256,256] f32 in [0,1]; bin_vals [64] = linspace(-1,1).
// hist[nc][b] = sum_p exp(-((2x-1)-b)^2/(2*0.02^2)), normalized per nc.
//
// R17 = R16 mainloop (6-bin pair window, 2-px batched RMW with register
// collision forwarding, MLP=8 front-batched LDG) at NT=256, SPLITS=16:
// same 384-block grid, 5.2 warps/SMSP (2x latency hiding). 64KB dynamic hist;
// __launch_bounds__(256, 1) pins the register budget so ptxas keeps the
// R16-style schedule (R12's collapse to 32 regs is the known failure mode).

#define NC_TOTAL   24
#define PIX_PER_NC 65536
#define HB         64
#define SPLITS     16
#define CHUNK      4096
#define NT         256
#define NITER      (CHUNK / (4 * NT))    // 4 float4 loads per thread
#define NPAIR      32
#define ROWB       (NT * 8)              // bytes per pair-row

#define DS    1.34812984f
#define TWO_D 2.69625968f
#define C1_  0.2837213f
#define C2_  6.479897e-3f
#define C3_  1.191316e-5f
#define C4_  1.763085e-9f
#define C5_  2.100399e-14f

#define SMEM_BYTES (NPAIR * NT * 8)      // 64KB dynamic hist

__device__ float    g_part[NC_TOTAL * SPLITS * HB];
__device__ unsigned g_cnt[NC_TOTAL];

__device__ __forceinline__ float ex2f(float a) {
    float r;
    asm("ex2.approx.ftz.f32 %0, %1;" : "=f"(r) : "f"(a));
    return r;
}
__device__ __forceinline__ uint32_t smem_u32(const void* p) {
    uint32_t a;
    asm("{ .reg .u64 t; cvta.to.shared.u64 t, %1; cvt.u32.u64 %0, t; }"
        : "=r"(a) : "l"(p));
    return a;
}
#define LDS2(h, addr) \
    asm volatile("ld.shared.v2.f32 {%0,%1}, [%2];" \
                 : "=f"((h).x), "=f"((h).y) : "r"(addr))
#define STS2(addr, v) \
    asm volatile("st.shared.v2.f32 [%0], {%1,%2};" \
                 :: "r"(addr), "f"((v).x), "f"((v).y) : "memory")

__device__ __forceinline__ float2 add2(float2 a, float2 b) {
    return make_float2(a.x + b.x, a.y + b.y);
}

struct PxW { int p0; float2 w0, w1, w2; };

__device__ __forceinline__ PxW px_weights(float vf) {
    PxW r;
    float u  = vf * 63.0f;
    int   jc = min(max(__float2int_rn(u), 2), 61);
    r.p0     = (jc - 2) >> 1;
    float ds = fmaf((float)r.p0, -TWO_D, u * DS);
    float A  = ex2f(-ds * ds);
    float B  = ex2f(ds * TWO_D);
    float B2 = B * B;
    float B3 = B2 * B;
    float AB4 = A * (B2 * B2);
    r.w0 = make_float2(A,              A * (B  * C1_));
    r.w1 = make_float2(A * (B2 * C2_), A * (B3 * C3_));
    r.w2 = make_float2(AB4 * C4_,      AB4 * (B * C5_));
    return r;
}

__global__ __launch_bounds__(NT, 1) void hist_fused_kernel(
    const float* __restrict__ x, const float* __restrict__ bin_vals,
    float* __restrict__ out)
{
    extern __shared__ float2 hist2[];      // [NPAIR][NT], 64KB dynamic
    __shared__ float2 racc2[NT];
    __shared__ float  ws[2];
    __shared__ int    slast;

    const int nc    = blockIdx.y;
    const int split = blockIdx.x;
    const int tid   = threadIdx.x;

    const uint32_t hbase = smem_u32(hist2) + tid * 8;

    // Front-batch the block's 16KB input: 4 independent LDG.128 per thread.
    const float4* xp = reinterpret_cast<const float4*>(
        x + (size_t)nc * PIX_PER_NC + (size_t)split * CHUNK);
    float4 vin[NITER];
#pragma unroll
    for (int i = 0; i < NITER; ++i)
        vin[i] = xp[tid + i * NT];

    // Zero hist while loads are in flight (16 STS.128 per thread).
    {
        float4* hz = reinterpret_cast<float4*>(hist2);
#pragma unroll
        for (int i = 0; i < (NPAIR * NT / 2) / NT; ++i)
            hz[tid + i * NT] = make_float4(0.f, 0.f, 0.f, 0.f);
    }
    __syncthreads();

#pragma unroll
    for (int it = 0; it < NITER; ++it) {
        float4 v = vin[it];
        float pa_[2] = {v.x, v.z};
        float pb_[2] = {v.y, v.w};
#pragma unroll
        for (int h = 0; h < 2; ++h) {
            PxW a = px_weights(pa_[h]);
            PxW b = px_weights(pb_[h]);

            uint32_t aa = hbase + (uint32_t)a.p0 * ROWB;
            uint32_t ab = hbase + (uint32_t)b.p0 * ROWB;

            // Batched loads: one exposed LDS latency for both pixels.
            float2 ha0, ha1, ha2, hb0, hb1, hb2;
            LDS2(ha0, aa);
            LDS2(ha1, aa + ROWB);
            LDS2(ha2, aa + 2 * ROWB);
            LDS2(hb0, ab);
            LDS2(hb1, ab + ROWB);
            LDS2(hb2, ab + 2 * ROWB);

            float2 na0 = add2(ha0, a.w0);
            float2 na1 = add2(ha1, a.w1);
            float2 na2 = add2(ha2, a.w2);

            // Collision forwarding: b row k aliases a row d+k (d = p0b-p0a).
            int d = b.p0 - a.p0;
            bool e0 = (d == 0), e1 = (d == 1), e2 = (d == 2);
            bool m1 = (d == -1), m2 = (d == -2);
            float2 f0 = e0 ? na0 : (e1 ? na1 : (e2 ? na2 : hb0));
            float2 f1 = m1 ? na0 : (e0 ? na1 : (e1 ? na2 : hb1));
            float2 f2 = m2 ? na0 : (m1 ? na1 : (e0 ? na2 : hb2));
            f0 = add2(f0, b.w0);
            f1 = add2(f1, b.w1);
            f2 = add2(f2, b.w2);

            // a stores first, then b (b carries forwarded totals on collision).
            STS2(aa, na0);
            STS2(aa + ROWB, na1);
            STS2(aa + 2 * ROWB, na2);
            STS2(ab, f0);
            STS2(ab + ROWB, f1);
            STS2(ab + 2 * ROWB, f2);
        }
    }
    __syncthreads();

    // Reduce phase 1 (float4 view: 4096 float4; pair P owns [P*128, P*128+127]).
    // Thread (P = tid>>3, eighth tid&7) sums 16 float4s, rotated.
    {
        const float4* fv = reinterpret_cast<const float4*>(hist2);
        const int P  = tid >> 3;
        const int jb = (tid & 7) * 16;
        float4 acc = make_float4(0.f, 0.f, 0.f, 0.f);
#pragma unroll
        for (int i = 0; i < 16; ++i) {
            int k = jb + ((i + tid) & 15);
            float4 hv = fv[P * (NT / 2) + k];
            acc.x += hv.x; acc.y += hv.y; acc.z += hv.z; acc.w += hv.w;
        }
        racc2[tid] = make_float2(acc.x + acc.z, acc.y + acc.w);  // (bin 2P, 2P+1)
    }
    __syncthreads();

    // Reduce phase 2: bin b sums its 8 partials.
    if (tid < HB) {
        const int pr = tid >> 1, comp = tid & 1;
        const float* rf = reinterpret_cast<const float*>(racc2);
        float s = 0.0f;
#pragma unroll
        for (int k = 0; k < 8; ++k)
            s += rf[(pr * 8 + k) * 2 + comp];
        g_part[((size_t)nc * SPLITS + split) * HB + tid] = s;
    }
    __syncthreads();

    // Last block per nc reduces + normalizes.
    if (tid == 0) {
        __threadfence();
        unsigned old = atomicAdd(&g_cnt[nc], 1u);
        slast = (old == SPLITS - 1);
    }
    __syncthreads();
    if (!slast) return;
    __threadfence();

    float bsum = 0.0f;
    if (tid < HB) {
        const float* p = g_part + (size_t)nc * SPLITS * HB + tid;
#pragma unroll
        for (int sp = 0; sp < SPLITS; ++sp)
            bsum += p[(size_t)sp * HB];
    }
    float v = (tid < HB) ? bsum : 0.0f;
    float r = v;
#pragma unroll
    for (int o = 16; o; o >>= 1) r += __shfl_xor_sync(0xffffffffu, r, o);
    if (tid == 0)  ws[0] = r;
    if (tid == 32) ws[1] = r;
    __syncthreads();
    float tot = ws[0] + ws[1];

    if (tid < HB)
        out[nc * HB + tid] = v / (tot + 1e-8f);

    if (tid == 0) g_cnt[nc] = 0;   // reset for next graph replay
}

extern "C" void kernel_launch(void* const* d_in, const int* in_sizes, int n_in,
                              void* d_out, int out_size) {
    const float* x        = (const float*)d_in[0];
    const float* bin_vals = (const float*)d_in[1];
    float* out            = (float*)d_out;

    cudaFuncSetAttribute(hist_fused_kernel,
                         cudaFuncAttributeMaxDynamicSharedMemorySize,
                         SMEM_BYTES);

    dim3 grid(SPLITS, NC_TOTAL);
    hist_fused_kernel<<<grid, NT, SMEM_BYTES>>>(x, bin_vals, out);
}